// round 13
// baseline (speedup 1.0000x reference)
#include <cuda_runtime.h>
#include <math.h>

#define NT    256
#define NBLK  1184
#define BATCH 50000
#define NPAIR (BATCH / 2)

// ---- shared memory layout (float offsets), 22896 floats = 91.6 KB/CTA ----
// bi-BLOCKED rows: AT row = bi*64 + ch, SIG row = bi*32 + ch.
// The two halves (bi=0: tids 0..127, bi=1: tids 128..255) are fully
// independent after init; they sync via named barriers 1+bi only.
#define O_ISF 0        // ISFT fp32 [p=96][k, stride 52], zero pads (p>=90, k>=45)
#define O_SFT 4992     // SFTT fp32 [k=48][p, stride 100], zero pads (k>=45, p>=90)
#define O_SC  9792     // scale[45] (pad 48)
#define O_AT  9840     // unified x / T / gemm2-out [128 rows][52]
#define O_SIG 16496    // sig [64 rows][100]
#define SMEM_FLOATS 22896
#define SMEM_BYTES  (SMEM_FLOATS * 4)

#define ST 52
#define SS 100

__device__ __forceinline__ void hbar(int bi) {
    asm volatile("bar.sync %0, 128;" :: "r"(1 + bi) : "memory");
}

// ---- tf32 truncation split: 2 fixed-lat ops ----
__device__ __forceinline__ void split_tf32(float x, unsigned &hi, unsigned &lo) {
    unsigned xb = __float_as_uint(x);
    hi = xb & 0xFFFFE000u;
    lo = __float_as_uint(x - __uint_as_float(hi));
}
__device__ __forceinline__ void mma8(float d[4], const unsigned a[4], const unsigned b[2]) {
    asm volatile(
        "mma.sync.aligned.m16n8k8.row.col.f32.tf32.tf32.f32 "
        "{%0,%1,%2,%3}, {%4,%5,%6,%7}, {%8,%9}, {%0,%1,%2,%3};"
        : "+f"(d[0]), "+f"(d[1]), "+f"(d[2]), "+f"(d[3])
        : "r"(a[0]), "r"(a[1]), "r"(a[2]), "r"(a[3]), "r"(b[0]), "r"(b[1]));
}

// sconv k-tiles aligned to degree-group boundaries (single ls_idx per tile)
__constant__ int c_tk0[15] = {0, 1, 5, 6, 10, 14, 15, 19, 23, 27, 28, 32, 36, 40, 44};
__constant__ int c_tkl[15] = {1, 4, 1, 4, 4, 1, 4, 4, 4, 1, 4, 4, 4, 4, 1};
__constant__ int c_td[15]  = {0, 1, 1, 2, 2, 2, 3, 3, 3, 3, 4, 4, 4, 4, 4};

// sconv per half: reads A rows bi*64+c, writes T rows bi*64+och (in-place,
// internal named barrier). 128 threads, SLOTS <= 120.
template <int Cin, int Cout, int OT>
__device__ __forceinline__ void sconv_step(float* sm, const float* __restrict__ gw,
                                           int th, int bi)
{
    constexpr int SLOTS = (Cout / OT) * 15;
    const int kt = th % 15;
    const int ot = th / 15;
    const int k0   = c_tk0[kt];
    const int klen = c_tkl[kt];
    const int d    = c_td[kt];

    float acc[OT][4];
#pragma unroll
    for (int i = 0; i < OT; i++)
#pragma unroll
        for (int j = 0; j < 4; j++) acc[i][j] = 0.f;

    if (th < SLOTS) {
        const float* __restrict__ A = sm + O_AT + (bi * 64) * ST + k0;
        const float* __restrict__ W = gw + (ot * OT) * (Cin * 5) + d;
#pragma unroll 4
        for (int c = 0; c < Cin; c++) {
            float xv[4];
#pragma unroll
            for (int j = 0; j < 4; j++) xv[j] = A[c * ST + j];   // k0+3 <= 47 < 52
#pragma unroll
            for (int i = 0; i < OT; i++) {
                float w = __ldg(W + i * (Cin * 5) + c * 5);
#pragma unroll
                for (int j = 0; j < 4; j++) acc[i][j] = fmaf(w, xv[j], acc[i][j]);
            }
        }
    }
    hbar(bi);   // all A reads done before T overwrites the same buffer

    if (th < SLOTS) {
        float* __restrict__ Tp = sm + O_AT + (bi * 64 + ot * OT) * ST + k0;
#pragma unroll
        for (int i = 0; i < OT; i++)
#pragma unroll
            for (int j = 0; j < 4; j++)
                if (j < klen) Tp[i * ST + j] = acc[i][j] * sm[O_SC + k0 + j];
    }
}

// GEMM1 per half (4 warps): sig[m][p] = relu( sum_k T[trow0+m][k]*ISF[k][p] )
// K=48, N=96. MW=2: mw=w&1 (2 m16-tiles), nw=w>>1 (2 groups x 48 cols, 6 nt).
// MW=1: mw=0, nw=w (4 groups x 24 cols, 3 nt).
template <int MW>
__device__ __forceinline__ void gemm1_mma(float* sm, int trow0, int srow0, int w, int lane)
{
    constexpr int NTC = (MW == 2) ? 6 : 3;
    const int mw = (MW == 2) ? (w & 1) : 0;
    const int nw = (MW == 2) ? (w >> 1) : w;
    const int g = lane >> 2, t = lane & 3;

    float d[NTC][4];
#pragma unroll
    for (int nt = 0; nt < NTC; nt++)
#pragma unroll
        for (int r = 0; r < 4; r++) d[nt][r] = 0.f;

    const float* Tb = sm + O_AT + (trow0 + mw * 16) * ST;
#pragma unroll
    for (int kc = 0; kc < 6; kc++) {
        const int k0 = kc * 8;
        float a0 = Tb[g * ST + k0 + t];
        float a1 = Tb[(g + 8) * ST + k0 + t];
        float a2 = Tb[g * ST + k0 + t + 4];
        float a3 = Tb[(g + 8) * ST + k0 + t + 4];
        unsigned ahi[4], alo[4];
        split_tf32(a0, ahi[0], alo[0]);
        split_tf32(a1, ahi[1], alo[1]);
        split_tf32(a2, ahi[2], alo[2]);
        split_tf32(a3, ahi[3], alo[3]);
#pragma unroll
        for (int nt = 0; nt < NTC; nt++) {
            const int n0 = nw * (8 * NTC) + nt * 8;
            float b0 = sm[O_ISF + (n0 + g) * ST + k0 + t];
            float b1 = sm[O_ISF + (n0 + g) * ST + k0 + t + 4];
            unsigned bh[2], bl[2];
            split_tf32(b0, bh[0], bl[0]);
            split_tf32(b1, bh[1], bl[1]);
            mma8(d[nt], ahi, bh);
            mma8(d[nt], ahi, bl);
            mma8(d[nt], alo, bh);
        }
    }
#pragma unroll
    for (int nt = 0; nt < NTC; nt++) {
        const int n0 = nw * (8 * NTC) + nt * 8;
        const int row = srow0 + mw * 16 + g;
        float2 v0 = make_float2(fmaxf(d[nt][0], 0.f), fmaxf(d[nt][1], 0.f));
        float2 v1 = make_float2(fmaxf(d[nt][2], 0.f), fmaxf(d[nt][3], 0.f));
        *reinterpret_cast<float2*>(sm + O_SIG + row * SS + n0 + 2 * t) = v0;
        *reinterpret_cast<float2*>(sm + O_SIG + (row + 8) * SS + n0 + 2 * t) = v1;
    }
}

// GEMM2 per half (4 warps): AT[arow0+m][k] = sum_p sig[srow0+m][p]*SFT[p][k]
// K=96, N=48. mw=w>>1 (m16-tiles, active if < MTILES), nw=w&1 (2 x 24 cols).
// Stores cols 0..47 (45..47 get zeros from SFT zero rows -> pad maintained).
template <int MTILES>
__device__ __forceinline__ void gemm2_mma(float* sm, int arow0, int srow0, int w, int lane)
{
    const int mw = w >> 1, nw = w & 1;
    if (mw < MTILES) {
        const int g = lane >> 2, t = lane & 3;
        const int m0 = mw * 16;
        float d[3][4];
#pragma unroll
        for (int nt = 0; nt < 3; nt++)
#pragma unroll
            for (int r = 0; r < 4; r++) d[nt][r] = 0.f;

#pragma unroll
        for (int pc = 0; pc < 12; pc++) {
            const int p0 = pc * 8;
            unsigned ahi[4], alo[4];
            float a0 = sm[O_SIG + (srow0 + m0 + g) * SS + p0 + t];
            float a1 = sm[O_SIG + (srow0 + m0 + g + 8) * SS + p0 + t];
            float a2 = sm[O_SIG + (srow0 + m0 + g) * SS + p0 + t + 4];
            float a3 = sm[O_SIG + (srow0 + m0 + g + 8) * SS + p0 + t + 4];
            split_tf32(a0, ahi[0], alo[0]);
            split_tf32(a1, ahi[1], alo[1]);
            split_tf32(a2, ahi[2], alo[2]);
            split_tf32(a3, ahi[3], alo[3]);
#pragma unroll
            for (int nt = 0; nt < 3; nt++) {
                const int n0 = nw * 24 + nt * 8;
                float b0 = sm[O_SFT + (n0 + g) * SS + p0 + t];
                float b1 = sm[O_SFT + (n0 + g) * SS + p0 + t + 4];
                unsigned bh[2], bl[2];
                split_tf32(b0, bh[0], bl[0]);
                split_tf32(b1, bh[1], bl[1]);
                mma8(d[nt], ahi, bh);
                mma8(d[nt], ahi, bl);
                mma8(d[nt], alo, bh);
            }
        }
#pragma unroll
        for (int nt = 0; nt < 3; nt++) {
            const int n0 = nw * 24 + nt * 8;
            const int col = n0 + 2 * t;     // <= 46, col+1 <= 47 < ST
            *reinterpret_cast<float2*>(sm + O_AT + (arow0 + m0 + g) * ST + col) =
                make_float2(d[nt][0], d[nt][1]);
            *reinterpret_cast<float2*>(sm + O_AT + (arow0 + m0 + g + 8) * ST + col) =
                make_float2(d[nt][2], d[nt][3]);
        }
    }
}

template <int Cin, int Cout, int OT>
__device__ __forceinline__ void run_layer(float* sm, const float* __restrict__ gw,
                                          int th, int bi, int w, int lane)
{
    sconv_step<Cin, Cout, OT>(sm, gw, th, bi);   // internal named barrier
    hbar(bi);
    constexpr int NCHB = (Cout + 31) / 32;
    constexpr int CH = (Cout < 32) ? Cout : 32;
    constexpr int MWx = (CH >= 32) ? 2 : 1;
#pragma unroll
    for (int cb = 0; cb < NCHB; cb++) {
        gemm1_mma<MWx>(sm, bi * 64 + cb * 32, bi * 32, w, lane);
        hbar(bi);
        gemm2_mma<MWx>(sm, bi * 64 + cb * 32, bi * 32, w, lane);
        hbar(bi);
    }
}

extern "C" __global__ void __launch_bounds__(NT, 2)
scnn_kernel(const float* __restrict__ x, const float* __restrict__ sft,
            const float* __restrict__ isft,
            const float* __restrict__ w1, const float* __restrict__ w2,
            const float* __restrict__ w3, const float* __restrict__ w4,
            const float* __restrict__ w5, const float* __restrict__ w6,
            float* __restrict__ out)
{
    extern __shared__ float sm[];
    const int tid = threadIdx.x;

    // ---- stage ISFT fp32 [p][k] stride 52, zero pads ----
    for (int i = tid; i < 96 * ST; i += NT) {
        int p = i / ST, k = i - p * ST;
        sm[O_ISF + i] = (p < 90 && k < 45) ? isft[p * 45 + k] : 0.f;
    }
    // ---- stage SFTT fp32 [k][p] stride 100, zero pads ----
    for (int i = tid; i < 48 * SS; i += NT) {
        int k = i / SS, p = i - k * SS;
        sm[O_SFT + i] = (k < 45 && p < 90) ? sft[k * 90 + p] : 0.f;
    }
    if (tid < 45) {
        int k = tid;
        int dd = (k >= 28) ? 4 : (k >= 15) ? 3 : (k >= 6) ? 2 : (k >= 1) ? 1 : 0;
        sm[O_SC + k] = sqrtf(3.14159265358979323846f / (float)(4 * dd + 1));
    }
    // ---- zero AT pad cols 45..51 for all 128 rows ----
    for (int i = tid; i < 128 * 7; i += NT) {
        int r = i / 7, c = 45 + (i - (i / 7) * 7);
        sm[O_AT + r * ST + c] = 0.f;
    }
    __syncthreads();   // last full-CTA barrier; halves are independent below

    const int bi   = tid >> 7;       // half id: 0 or 1
    const int th   = tid & 127;      // thread within half
    const int w    = th >> 5;        // warp within half: 0..3
    const int lane = th & 31;

    // ---- persistent stride loop; each half handles its own batch element ----
    for (int pair = blockIdx.x; pair < NPAIR; pair += gridDim.x) {
        const int b = pair * 2 + bi;

        // load x: rows bi*64 + c, cols 0..44
        for (int i = th; i < 180; i += 128) {
            int c = i / 45, k = i - c * 45;
            sm[O_AT + (bi * 64 + c) * ST + k] = x[b * 180 + i];
        }
        hbar(bi);

        run_layer<4,  16, 2>(sm, w1, th, bi, w, lane);
        run_layer<16, 32, 4>(sm, w2, th, bi, w, lane);
        run_layer<32, 64, 8>(sm, w3, th, bi, w, lane);
        run_layer<64, 32, 4>(sm, w4, th, bi, w, lane);
        run_layer<32, 16, 2>(sm, w5, th, bi, w, lane);
        run_layer<16, 4,  1>(sm, w6, th, bi, w, lane);

        // store output: rows bi*64 + c
        for (int i = th; i < 180; i += 128) {
            int c = i / 45, k = i - c * 45;
            out[b * 180 + i] = sm[O_AT + (bi * 64 + c) * ST + k];
        }
        hbar(bi);   // protect AT before next iteration's load
    }
}

extern "C" void kernel_launch(void* const* d_in, const int* in_sizes, int n_in,
                              void* d_out, int out_size)
{
    cudaFuncSetAttribute(scnn_kernel, cudaFuncAttributeMaxDynamicSharedMemorySize,
                         SMEM_BYTES);
    scnn_kernel<<<NBLK, NT, SMEM_BYTES>>>(
        (const float*)d_in[0], (const float*)d_in[1], (const float*)d_in[2],
        (const float*)d_in[3], (const float*)d_in[4], (const float*)d_in[5],
        (const float*)d_in[6], (const float*)d_in[7], (const float*)d_in[8],
        (float*)d_out);
}

// round 14
// speedup vs baseline: 1.1841x; 1.1841x over previous
#include <cuda_runtime.h>
#include <math.h>

#define NT    256
#define NBLK  1184
#define BATCH 50000
#define BT    2
#define NPAIR (BATCH / BT)

// ---- shared memory layout (float offsets), 24240 floats = 97.0 KB/CTA ----
// Interleaved rows (R12): AT row = ch*2+bi, SIG row = ch*2+bi.
// Strides chosen for conflict-free float2 (LDS.64) fragment loads:
//   56:  g*56 mod 32 = {0,24,16,8}  -> half-warp covers all 32 banks
//   104: g*104 mod 32 = {0,8,16,24} -> same
#define O_ISF 0        // ISFT fp32 [p=96][k, stride 56], zero pads (p>=90, k>=45)
#define O_SFT 5376     // SFTT fp32 [k=48][p, stride 104], zero pads (k>=45, p>=90)
#define O_SC  10368    // scale[45] (pad 48)
#define O_AT  10416    // unified x / T / gemm2-out [128 rows][56], cols 45..55 zero
#define O_SIG 17584    // sig [64 rows][104]
#define SMEM_FLOATS 24240
#define SMEM_BYTES  (SMEM_FLOATS * 4)

#define ST 56
#define SS 104

// ---- bf16 split of an adjacent-k float2: hi = truncate-to-bf16 (exact lo),
// lo = rounded remainder. 1 PRMT + 2 LOP3 + 2 FADD + 1 CVT.
__device__ __forceinline__ void bsplit(float2 v, unsigned &hp, unsigned &lp) {
    unsigned xb = __float_as_uint(v.x);
    unsigned yb = __float_as_uint(v.y);
    asm("prmt.b32 %0, %1, %2, 0x7632;" : "=r"(hp) : "r"(xb), "r"(yb));
    float lx = v.x - __uint_as_float(xb & 0xFFFF0000u);
    float ly = v.y - __uint_as_float(yb & 0xFFFF0000u);
    asm("cvt.rn.bf16x2.f32 %0, %1, %2;" : "=r"(lp) : "f"(ly), "f"(lx));
}
__device__ __forceinline__ void mma16(float d[4], const unsigned a[4], const unsigned b[2]) {
    asm volatile(
        "mma.sync.aligned.m16n8k16.row.col.f32.bf16.bf16.f32 "
        "{%0,%1,%2,%3}, {%4,%5,%6,%7}, {%8,%9}, {%0,%1,%2,%3};"
        : "+f"(d[0]), "+f"(d[1]), "+f"(d[2]), "+f"(d[3])
        : "r"(a[0]), "r"(a[1]), "r"(a[2]), "r"(a[3]), "r"(b[0]), "r"(b[1]));
}

// sconv k-tiles aligned to degree-group boundaries (single ls_idx per tile)
__constant__ int c_tk0[15] = {0, 1, 5, 6, 10, 14, 15, 19, 23, 27, 28, 32, 36, 40, 44};
__constant__ int c_tkl[15] = {1, 4, 1, 4, 4, 1, 4, 4, 4, 1, 4, 4, 4, 4, 1};
__constant__ int c_td[15]  = {0, 1, 1, 2, 2, 2, 3, 3, 3, 3, 4, 4, 4, 4, 4};

// sconv (two-phase, in-place in AT, fp32): read A rows c*2+bi, barrier,
// write T rows och*2+bi (cols 0..44; 45..55 stay zero).
template <int Cin, int Cout, int OT>
__device__ __forceinline__ void sconv_step(float* sm, const float* __restrict__ gw, int tid)
{
    constexpr int SLOTS = BT * (Cout / OT) * 15;
    const int kt = tid % 15;
    const int bi = (tid / 15) & 1;
    const int ot = tid / (15 * BT);
    const int k0   = c_tk0[kt];
    const int klen = c_tkl[kt];
    const int d    = c_td[kt];

    float acc[OT][4];
#pragma unroll
    for (int i = 0; i < OT; i++)
#pragma unroll
        for (int j = 0; j < 4; j++) acc[i][j] = 0.f;

    if (tid < SLOTS) {
        const float* __restrict__ A = sm + O_AT + bi * ST + k0;
        const float* __restrict__ W = gw + (ot * OT) * (Cin * 5) + d;
#pragma unroll 4
        for (int c = 0; c < Cin; c++) {
            float xv[4];
#pragma unroll
            for (int j = 0; j < 4; j++) xv[j] = A[c * (2 * ST) + j];   // k<=47<56
#pragma unroll
            for (int i = 0; i < OT; i++) {
                float w = __ldg(W + i * (Cin * 5) + c * 5);
#pragma unroll
                for (int j = 0; j < 4; j++) acc[i][j] = fmaf(w, xv[j], acc[i][j]);
            }
        }
    }
    __syncthreads();   // all A reads done before T overwrites the same buffer

    if (tid < SLOTS) {
        float* __restrict__ Tp = sm + O_AT + ((ot * OT) * 2 + bi) * ST + k0;
#pragma unroll
        for (int i = 0; i < OT; i++)
#pragma unroll
            for (int j = 0; j < 4; j++)
                if (j < klen) Tp[i * (2 * ST) + j] = acc[i][j] * sm[O_SC + k0 + j];
    }
}

// GEMM1 (bf16 x3, k16): sig[m][p] = relu( sum_k T[trow0+m][k]*ISF[k][p] )
// K=48 (3 kc16), N=96. 8 warps: mw=w&1 (MT m16-tiles), nw=w>>1 (4 x 24 cols).
template <int MT, int MW>
__device__ __forceinline__ void gemm1_mma(float* sm, int trow0, int w, int lane)
{
    const int mw = w & 1, nw = w >> 1;
    if (mw < MW) {
        const int g = lane >> 2, t = lane & 3;
        float d[MT][3][4];
#pragma unroll
        for (int i = 0; i < MT; i++)
#pragma unroll
            for (int nt = 0; nt < 3; nt++)
#pragma unroll
                for (int r = 0; r < 4; r++) d[i][nt][r] = 0.f;

        const float* Tb = sm + O_AT + trow0 * ST;
#pragma unroll
        for (int kc = 0; kc < 3; kc++) {
            const int k0 = kc * 16;
            unsigned ah[MT][4], al[MT][4];
#pragma unroll
            for (int i = 0; i < MT; i++) {
                const int m0 = (mw * MT + i) * 16;
                float2 v0 = *reinterpret_cast<const float2*>(Tb + (m0 + g) * ST + k0 + 2 * t);
                float2 v1 = *reinterpret_cast<const float2*>(Tb + (m0 + g + 8) * ST + k0 + 2 * t);
                float2 v2 = *reinterpret_cast<const float2*>(Tb + (m0 + g) * ST + k0 + 2 * t + 8);
                float2 v3 = *reinterpret_cast<const float2*>(Tb + (m0 + g + 8) * ST + k0 + 2 * t + 8);
                bsplit(v0, ah[i][0], al[i][0]);
                bsplit(v1, ah[i][1], al[i][1]);
                bsplit(v2, ah[i][2], al[i][2]);
                bsplit(v3, ah[i][3], al[i][3]);
            }
#pragma unroll
            for (int nt = 0; nt < 3; nt++) {
                const int n0 = nw * 24 + nt * 8;
                float2 u0 = *reinterpret_cast<const float2*>(sm + O_ISF + (n0 + g) * ST + k0 + 2 * t);
                float2 u1 = *reinterpret_cast<const float2*>(sm + O_ISF + (n0 + g) * ST + k0 + 2 * t + 8);
                unsigned bh[2], bl[2];
                bsplit(u0, bh[0], bl[0]);
                bsplit(u1, bh[1], bl[1]);
#pragma unroll
                for (int i = 0; i < MT; i++) {
                    mma16(d[i][nt], ah[i], bh);
                    mma16(d[i][nt], ah[i], bl);
                    mma16(d[i][nt], al[i], bh);
                }
            }
        }
#pragma unroll
        for (int i = 0; i < MT; i++) {
            const int m0 = (mw * MT + i) * 16;
#pragma unroll
            for (int nt = 0; nt < 3; nt++) {
                const int n0 = nw * 24 + nt * 8;
                float2 v0 = make_float2(fmaxf(d[i][nt][0], 0.f), fmaxf(d[i][nt][1], 0.f));
                float2 v1 = make_float2(fmaxf(d[i][nt][2], 0.f), fmaxf(d[i][nt][3], 0.f));
                *reinterpret_cast<float2*>(sm + O_SIG + (m0 + g) * SS + n0 + 2 * t) = v0;
                *reinterpret_cast<float2*>(sm + O_SIG + (m0 + g + 8) * SS + n0 + 2 * t) = v1;
            }
        }
    }
}

// GEMM2 (bf16 x3, k16): AT[arow0+m][k] = sum_p sig[m][p]*SFT[p][k]
// K=96 (6 kc16), N=48. 8 warps: mw=w>>1 (m16-tile if < MTILES), nw=w&1 (2 x 24).
// Stores cols 0..47 (45..47 zeros from SFT zero rows -> pad maintained).
template <int MTILES, int FULL>
__device__ __forceinline__ void gemm2_mma(float* sm, int arow0, int w, int lane)
{
    const int mw = w >> 1, nw = w & 1;
    if (mw < MTILES) {
        const int g = lane >> 2, t = lane & 3;
        const int m0 = mw * 16;
        float d[3][4];
#pragma unroll
        for (int nt = 0; nt < 3; nt++)
#pragma unroll
            for (int r = 0; r < 4; r++) d[nt][r] = 0.f;

#pragma unroll
        for (int pc = 0; pc < 6; pc++) {
            const int p0 = pc * 16;
            unsigned ah[4], al[4];
            float2 v0 = *reinterpret_cast<const float2*>(sm + O_SIG + (m0 + g) * SS + p0 + 2 * t);
            float2 v1 = *reinterpret_cast<const float2*>(sm + O_SIG + (m0 + g + 8) * SS + p0 + 2 * t);
            float2 v2 = *reinterpret_cast<const float2*>(sm + O_SIG + (m0 + g) * SS + p0 + 2 * t + 8);
            float2 v3 = *reinterpret_cast<const float2*>(sm + O_SIG + (m0 + g + 8) * SS + p0 + 2 * t + 8);
            bsplit(v0, ah[0], al[0]);
            bsplit(v1, ah[1], al[1]);
            bsplit(v2, ah[2], al[2]);
            bsplit(v3, ah[3], al[3]);
#pragma unroll
            for (int nt = 0; nt < 3; nt++) {
                const int n0 = nw * 24 + nt * 8;
                float2 u0 = *reinterpret_cast<const float2*>(sm + O_SFT + (n0 + g) * SS + p0 + 2 * t);
                float2 u1 = *reinterpret_cast<const float2*>(sm + O_SFT + (n0 + g) * SS + p0 + 2 * t + 8);
                unsigned bh[2], bl[2];
                bsplit(u0, bh[0], bl[0]);
                bsplit(u1, bh[1], bl[1]);
                mma16(d[nt], ah, bh);
                mma16(d[nt], ah, bl);
                mma16(d[nt], al, bh);
            }
        }
#pragma unroll
        for (int nt = 0; nt < 3; nt++) {
            const int n0 = nw * 24 + nt * 8;
            const int col = n0 + 2 * t;     // <= 46, col+1 <= 47 < ST
            *reinterpret_cast<float2*>(sm + O_AT + (arow0 + m0 + g) * ST + col) =
                make_float2(d[nt][0], d[nt][1]);
            if (FULL)
                *reinterpret_cast<float2*>(sm + O_AT + (arow0 + m0 + g + 8) * ST + col) =
                    make_float2(d[nt][2], d[nt][3]);
        }
    }
}

template <int Cin, int Cout, int OT>
__device__ __forceinline__ void run_layer(float* sm, const float* __restrict__ gw, int tid)
{
    sconv_step<Cin, Cout, OT>(sm, gw, tid);   // internal barrier
    __syncthreads();
    const int w = tid >> 5, lane = tid & 31;
    constexpr int NCHB = (Cout + 31) / 32;
    constexpr int M = BT * (Cout < 32 ? Cout : 32);
#pragma unroll
    for (int cb = 0; cb < NCHB; cb++) {
        if constexpr (M == 64)       gemm1_mma<2, 2>(sm, cb * 64, w, lane);
        else if constexpr (M == 32)  gemm1_mma<1, 2>(sm, 0, w, lane);
        else                         gemm1_mma<1, 1>(sm, 0, w, lane);
        __syncthreads();
        if constexpr (M == 64)       gemm2_mma<4, 1>(sm, cb * 64, w, lane);
        else if constexpr (M == 32)  gemm2_mma<2, 1>(sm, 0, w, lane);
        else                         gemm2_mma<1, 0>(sm, 0, w, lane);
        __syncthreads();
    }
}

extern "C" __global__ void __launch_bounds__(NT, 2)
scnn_kernel(const float* __restrict__ x, const float* __restrict__ sft,
            const float* __restrict__ isft,
            const float* __restrict__ w1, const float* __restrict__ w2,
            const float* __restrict__ w3, const float* __restrict__ w4,
            const float* __restrict__ w5, const float* __restrict__ w6,
            float* __restrict__ out)
{
    extern __shared__ float sm[];
    const int tid = threadIdx.x;

    // ---- stage ISFT fp32 [p][k] stride 56, zero pads ----
    for (int i = tid; i < 96 * ST; i += NT) {
        int p = i / ST, k = i - p * ST;
        sm[O_ISF + i] = (p < 90 && k < 45) ? isft[p * 45 + k] : 0.f;
    }
    // ---- stage SFTT fp32 [k][p] stride 104, zero pads ----
    for (int i = tid; i < 48 * SS; i += NT) {
        int k = i / SS, p = i - k * SS;
        sm[O_SFT + i] = (k < 45 && p < 90) ? sft[k * 90 + p] : 0.f;
    }
    if (tid < 45) {
        int k = tid;
        int dd = (k >= 28) ? 4 : (k >= 15) ? 3 : (k >= 6) ? 2 : (k >= 1) ? 1 : 0;
        sm[O_SC + k] = sqrtf(3.14159265358979323846f / (float)(4 * dd + 1));
    }
    // ---- zero AT pad cols 45..55 for all 128 rows ----
    for (int i = tid; i < 128 * 11; i += NT) {
        int r = i / 11, c = 45 + (i - (i / 11) * 11);
        sm[O_AT + r * ST + c] = 0.f;
    }
    __syncthreads();

    // ---- persistent stride loop over batch pairs ----
    for (int pair = blockIdx.x; pair < NPAIR; pair += gridDim.x) {
        const int b0 = pair * BT;

        // load x: rows c*2+bi, cols 0..44
        for (int i = tid; i < BT * 180; i += NT) {
            int bi = i / 180, r = i - bi * 180;
            int c = r / 45, k = r - c * 45;
            sm[O_AT + (c * 2 + bi) * ST + k] = x[(b0 + bi) * 180 + r];
        }
        __syncthreads();

        run_layer<4,  16, 2>(sm, w1, tid);
        run_layer<16, 32, 4>(sm, w2, tid);
        run_layer<32, 64, 8>(sm, w3, tid);
        run_layer<64, 32, 4>(sm, w4, tid);
        run_layer<32, 16, 2>(sm, w5, tid);
        run_layer<16, 4,  1>(sm, w6, tid);

        // store output: rows c*2+bi
        for (int i = tid; i < BT * 180; i += NT) {
            int bi = i / 180, r = i - bi * 180;
            int c = r / 45, k = r - c * 45;
            out[(b0 + bi) * 180 + r] = sm[O_AT + (c * 2 + bi) * ST + k];
        }
        __syncthreads();   // protect AT before next iteration's load
    }
}

extern "C" void kernel_launch(void* const* d_in, const int* in_sizes, int n_in,
                              void* d_out, int out_size)
{
    cudaFuncSetAttribute(scnn_kernel, cudaFuncAttributeMaxDynamicSharedMemorySize,
                         SMEM_BYTES);
    scnn_kernel<<<NBLK, NT, SMEM_BYTES>>>(
        (const float*)d_in[0], (const float*)d_in[1], (const float*)d_in[2],
        (const float*)d_in[3], (const float*)d_in[4], (const float*)d_in[5],
        (const float*)d_in[6], (const float*)d_in[7], (const float*)d_in[8],
        (float*)d_out);
}

// round 15
// speedup vs baseline: 1.2244x; 1.0340x over previous
#include <cuda_runtime.h>
#include <math.h>

#define NT    256
#define NBLK  1184
#define BATCH 50000
#define BT    2
#define NPAIR (BATCH / BT)

// ---- shared memory layout (32-bit word offsets), 24240 words = 97.0 KB/CTA ----
// Packed arrays store (hi,lo) bf16x2 pairs interleaved: word 2j = hi of
// elements (2j,2j+1), word 2j+1 = lo. uint2 load -> both MMA operands.
// Bank-perfect strides for uint2 half-warp phases: 56 (g*24 mod 32) and
// 104 (g*8 mod 32) tile all 32 banks.
#define O_ISF 0        // ISFT packed [p=96][56 w]   (24 k-pairs -> 48 w + pad)
#define O_SFT 5376     // SFTT packed [k=48][104 w]  (48 p-pairs -> 96 w + pad)
#define O_SC  10368    // scale[45] (pad 48)
#define O_AT  10416    // fp32 x / T / gemm2-out [128 rows][56], cols 45..55 zero
#define O_SIG 17584    // sig packed [64 rows][104 w]
#define SMEM_FLOATS 24240
#define SMEM_BYTES  (SMEM_FLOATS * 4)

#define ST 56
#define SS 104

// ---- bf16 split of adjacent pair: hi = truncate-to-bf16, lo = rn remainder ----
__device__ __forceinline__ void bsplit(float2 v, unsigned &hp, unsigned &lp) {
    unsigned xb = __float_as_uint(v.x);
    unsigned yb = __float_as_uint(v.y);
    asm("prmt.b32 %0, %1, %2, 0x7632;" : "=r"(hp) : "r"(xb), "r"(yb));
    float lx = v.x - __uint_as_float(xb & 0xFFFF0000u);
    float ly = v.y - __uint_as_float(yb & 0xFFFF0000u);
    asm("cvt.rn.bf16x2.f32 %0, %1, %2;" : "=r"(lp) : "f"(ly), "f"(lx));
}
__device__ __forceinline__ void mma16(float d[4], const unsigned a[4], const unsigned b[2]) {
    asm volatile(
        "mma.sync.aligned.m16n8k16.row.col.f32.bf16.bf16.f32 "
        "{%0,%1,%2,%3}, {%4,%5,%6,%7}, {%8,%9}, {%0,%1,%2,%3};"
        : "+f"(d[0]), "+f"(d[1]), "+f"(d[2]), "+f"(d[3])
        : "r"(a[0]), "r"(a[1]), "r"(a[2]), "r"(a[3]), "r"(b[0]), "r"(b[1]));
}

// sconv k-tiles aligned to degree-group boundaries (single ls_idx per tile)
__constant__ int c_tk0[15] = {0, 1, 5, 6, 10, 14, 15, 19, 23, 27, 28, 32, 36, 40, 44};
__constant__ int c_tkl[15] = {1, 4, 1, 4, 4, 1, 4, 4, 4, 1, 4, 4, 4, 4, 1};
__constant__ int c_td[15]  = {0, 1, 1, 2, 2, 2, 3, 3, 3, 3, 4, 4, 4, 4, 4};

// sconv (two-phase, in-place in AT, fp32)
template <int Cin, int Cout, int OT>
__device__ __forceinline__ void sconv_step(float* sm, const float* __restrict__ gw, int tid)
{
    constexpr int SLOTS = BT * (Cout / OT) * 15;
    const int kt = tid % 15;
    const int bi = (tid / 15) & 1;
    const int ot = tid / (15 * BT);
    const int k0   = c_tk0[kt];
    const int klen = c_tkl[kt];
    const int d    = c_td[kt];

    float acc[OT][4];
#pragma unroll
    for (int i = 0; i < OT; i++)
#pragma unroll
        for (int j = 0; j < 4; j++) acc[i][j] = 0.f;

    if (tid < SLOTS) {
        const float* __restrict__ A = sm + O_AT + bi * ST + k0;
        const float* __restrict__ W = gw + (ot * OT) * (Cin * 5) + d;
#pragma unroll 4
        for (int c = 0; c < Cin; c++) {
            float xv[4];
#pragma unroll
            for (int j = 0; j < 4; j++) xv[j] = A[c * (2 * ST) + j];
#pragma unroll
            for (int i = 0; i < OT; i++) {
                float w = __ldg(W + i * (Cin * 5) + c * 5);
#pragma unroll
                for (int j = 0; j < 4; j++) acc[i][j] = fmaf(w, xv[j], acc[i][j]);
            }
        }
    }
    __syncthreads();

    if (tid < SLOTS) {
        float* __restrict__ Tp = sm + O_AT + ((ot * OT) * 2 + bi) * ST + k0;
#pragma unroll
        for (int i = 0; i < OT; i++)
#pragma unroll
            for (int j = 0; j < 4; j++)
                if (j < klen) Tp[i * (2 * ST) + j] = acc[i][j] * sm[O_SC + k0 + j];
    }
}

// GEMM1 (bf16 x3, k16): sig[m][p] = relu( sum_k T[trow0+m][k]*ISF[k][p] )
// A: fp32 T, runtime split. B: pre-split packed. Epilogue stores packed sig.
template <int MT, int MW>
__device__ __forceinline__ void gemm1_mma(float* sm, int trow0, int w, int lane)
{
    const int mw = w & 1, nw = w >> 1;
    if (mw < MW) {
        const int g = lane >> 2, t = lane & 3;
        float d[MT][3][4];
#pragma unroll
        for (int i = 0; i < MT; i++)
#pragma unroll
            for (int nt = 0; nt < 3; nt++)
#pragma unroll
                for (int r = 0; r < 4; r++) d[i][nt][r] = 0.f;

        const float* Tb = sm + O_AT + trow0 * ST;
        const unsigned* ISFu = reinterpret_cast<const unsigned*>(sm) + O_ISF;
#pragma unroll
        for (int kc = 0; kc < 3; kc++) {
            const int k0 = kc * 16;
            unsigned ah[MT][4], al[MT][4];
#pragma unroll
            for (int i = 0; i < MT; i++) {
                const int m0 = (mw * MT + i) * 16;
                float2 v0 = *reinterpret_cast<const float2*>(Tb + (m0 + g) * ST + k0 + 2 * t);
                float2 v1 = *reinterpret_cast<const float2*>(Tb + (m0 + g + 8) * ST + k0 + 2 * t);
                float2 v2 = *reinterpret_cast<const float2*>(Tb + (m0 + g) * ST + k0 + 2 * t + 8);
                float2 v3 = *reinterpret_cast<const float2*>(Tb + (m0 + g + 8) * ST + k0 + 2 * t + 8);
                bsplit(v0, ah[i][0], al[i][0]);
                bsplit(v1, ah[i][1], al[i][1]);
                bsplit(v2, ah[i][2], al[i][2]);
                bsplit(v3, ah[i][3], al[i][3]);
            }
#pragma unroll
            for (int nt = 0; nt < 3; nt++) {
                const int n0 = nw * 24 + nt * 8;
                uint2 pb0 = *reinterpret_cast<const uint2*>(ISFu + (n0 + g) * ST + k0 + 2 * t);
                uint2 pb1 = *reinterpret_cast<const uint2*>(ISFu + (n0 + g) * ST + k0 + 2 * t + 8);
                unsigned bh[2] = {pb0.x, pb1.x};
                unsigned bl[2] = {pb0.y, pb1.y};
#pragma unroll
                for (int i = 0; i < MT; i++) {
                    mma16(d[i][nt], ah[i], bh);
                    mma16(d[i][nt], ah[i], bl);
                    mma16(d[i][nt], al[i], bh);
                }
            }
        }
        // epilogue: relu, split to packed (hi,lo) bf16 pairs
        unsigned* SIGu = reinterpret_cast<unsigned*>(sm) + O_SIG;
#pragma unroll
        for (int i = 0; i < MT; i++) {
            const int m0 = (mw * MT + i) * 16;
#pragma unroll
            for (int nt = 0; nt < 3; nt++) {
                const int n0 = nw * 24 + nt * 8;
                float2 v0 = make_float2(fmaxf(d[i][nt][0], 0.f), fmaxf(d[i][nt][1], 0.f));
                float2 v1 = make_float2(fmaxf(d[i][nt][2], 0.f), fmaxf(d[i][nt][3], 0.f));
                unsigned h0, l0, h1, l1;
                bsplit(v0, h0, l0);
                bsplit(v1, h1, l1);
                *reinterpret_cast<uint2*>(SIGu + (m0 + g) * SS + n0 + 2 * t) = make_uint2(h0, l0);
                *reinterpret_cast<uint2*>(SIGu + (m0 + g + 8) * SS + n0 + 2 * t) = make_uint2(h1, l1);
            }
        }
    }
}

// GEMM2 (bf16 x3, k16): AT[arow0+m][k] = sum_p sig[m][p]*SFT[p][k]
// A: pre-split packed sig. B: pre-split packed SFT. Zero runtime splits.
template <int MTILES, int FULL>
__device__ __forceinline__ void gemm2_mma(float* sm, int arow0, int w, int lane)
{
    const int mw = w >> 1, nw = w & 1;
    if (mw < MTILES) {
        const int g = lane >> 2, t = lane & 3;
        const int m0 = mw * 16;
        float d[3][4];
#pragma unroll
        for (int nt = 0; nt < 3; nt++)
#pragma unroll
            for (int r = 0; r < 4; r++) d[nt][r] = 0.f;

        const unsigned* SIGu = reinterpret_cast<const unsigned*>(sm) + O_SIG;
        const unsigned* SFTu = reinterpret_cast<const unsigned*>(sm) + O_SFT;
#pragma unroll
        for (int pc = 0; pc < 6; pc++) {
            const int p0 = pc * 16;
            uint2 pa0 = *reinterpret_cast<const uint2*>(SIGu + (m0 + g) * SS + p0 + 2 * t);
            uint2 pa1 = *reinterpret_cast<const uint2*>(SIGu + (m0 + g + 8) * SS + p0 + 2 * t);
            uint2 pa2 = *reinterpret_cast<const uint2*>(SIGu + (m0 + g) * SS + p0 + 2 * t + 8);
            uint2 pa3 = *reinterpret_cast<const uint2*>(SIGu + (m0 + g + 8) * SS + p0 + 2 * t + 8);
            unsigned ah[4] = {pa0.x, pa1.x, pa2.x, pa3.x};
            unsigned al[4] = {pa0.y, pa1.y, pa2.y, pa3.y};
#pragma unroll
            for (int nt = 0; nt < 3; nt++) {
                const int n0 = nw * 24 + nt * 8;
                uint2 pb0 = *reinterpret_cast<const uint2*>(SFTu + (n0 + g) * SS + p0 + 2 * t);
                uint2 pb1 = *reinterpret_cast<const uint2*>(SFTu + (n0 + g) * SS + p0 + 2 * t + 8);
                unsigned bh[2] = {pb0.x, pb1.x};
                unsigned bl[2] = {pb0.y, pb1.y};
                mma16(d[nt], ah, bh);
                mma16(d[nt], ah, bl);
                mma16(d[nt], al, bh);
            }
        }
#pragma unroll
        for (int nt = 0; nt < 3; nt++) {
            const int n0 = nw * 24 + nt * 8;
            const int col = n0 + 2 * t;     // <= 46, col+1 <= 47 < ST
            *reinterpret_cast<float2*>(sm + O_AT + (arow0 + m0 + g) * ST + col) =
                make_float2(d[nt][0], d[nt][1]);
            if (FULL)
                *reinterpret_cast<float2*>(sm + O_AT + (arow0 + m0 + g + 8) * ST + col) =
                    make_float2(d[nt][2], d[nt][3]);
        }
    }
}

template <int Cin, int Cout, int OT>
__device__ __forceinline__ void run_layer(float* sm, const float* __restrict__ gw, int tid)
{
    sconv_step<Cin, Cout, OT>(sm, gw, tid);   // internal barrier
    __syncthreads();
    const int w = tid >> 5, lane = tid & 31;
    constexpr int NCHB = (Cout + 31) / 32;
    constexpr int M = BT * (Cout < 32 ? Cout : 32);
#pragma unroll
    for (int cb = 0; cb < NCHB; cb++) {
        if constexpr (M == 64)       gemm1_mma<2, 2>(sm, cb * 64, w, lane);
        else if constexpr (M == 32)  gemm1_mma<1, 2>(sm, 0, w, lane);
        else                         gemm1_mma<1, 1>(sm, 0, w, lane);
        __syncthreads();
        if constexpr (M == 64)       gemm2_mma<4, 1>(sm, cb * 64, w, lane);
        else if constexpr (M == 32)  gemm2_mma<2, 1>(sm, 0, w, lane);
        else                         gemm2_mma<1, 0>(sm, 0, w, lane);
        __syncthreads();
    }
}

extern "C" __global__ void __launch_bounds__(NT, 2)
scnn_kernel(const float* __restrict__ x, const float* __restrict__ sft,
            const float* __restrict__ isft,
            const float* __restrict__ w1, const float* __restrict__ w2,
            const float* __restrict__ w3, const float* __restrict__ w4,
            const float* __restrict__ w5, const float* __restrict__ w6,
            float* __restrict__ out)
{
    extern __shared__ float sm[];
    unsigned* smu = reinterpret_cast<unsigned*>(sm);
    const int tid = threadIdx.x;

    // ---- stage ISFT pre-split packed: [p][24 k-pairs], stride 56 w ----
    for (int i = tid; i < 96 * 24; i += NT) {
        int p = i / 24, j = i - (i / 24) * 24;
        float f0 = (p < 90 && 2 * j < 45) ? isft[p * 45 + 2 * j] : 0.f;
        float f1 = (p < 90 && 2 * j + 1 < 45) ? isft[p * 45 + 2 * j + 1] : 0.f;
        unsigned h, l;
        bsplit(make_float2(f0, f1), h, l);
        smu[O_ISF + p * ST + 2 * j] = h;
        smu[O_ISF + p * ST + 2 * j + 1] = l;
    }
    // ---- stage SFTT pre-split packed: [k][48 p-pairs], stride 104 w ----
    for (int i = tid; i < 48 * 48; i += NT) {
        int k = i / 48, j = i - (i / 48) * 48;
        float f0 = (k < 45 && 2 * j < 90) ? sft[k * 90 + 2 * j] : 0.f;
        float f1 = (k < 45 && 2 * j + 1 < 90) ? sft[k * 90 + 2 * j + 1] : 0.f;
        unsigned h, l;
        bsplit(make_float2(f0, f1), h, l);
        smu[O_SFT + k * SS + 2 * j] = h;
        smu[O_SFT + k * SS + 2 * j + 1] = l;
    }
    if (tid < 45) {
        int k = tid;
        int dd = (k >= 28) ? 4 : (k >= 15) ? 3 : (k >= 6) ? 2 : (k >= 1) ? 1 : 0;
        sm[O_SC + k] = sqrtf(3.14159265358979323846f / (float)(4 * dd + 1));
    }
    // ---- zero AT pad cols 45..55 for all 128 rows ----
    for (int i = tid; i < 128 * 11; i += NT) {
        int r = i / 11, c = 45 + (i - (i / 11) * 11);
        sm[O_AT + r * ST + c] = 0.f;
    }
    __syncthreads();

    // ---- persistent stride loop over batch pairs ----
    for (int pair = blockIdx.x; pair < NPAIR; pair += gridDim.x) {
        const int b0 = pair * BT;

        // load x: rows c*2+bi, cols 0..44
        for (int i = tid; i < BT * 180; i += NT) {
            int bi = i / 180, r = i - bi * 180;
            int c = r / 45, k = r - c * 45;
            sm[O_AT + (c * 2 + bi) * ST + k] = x[(b0 + bi) * 180 + r];
        }
        __syncthreads();

        run_layer<4,  16, 2>(sm, w1, tid);
        run_layer<16, 32, 4>(sm, w2, tid);
        run_layer<32, 64, 8>(sm, w3, tid);
        run_layer<64, 32, 4>(sm, w4, tid);
        run_layer<32, 16, 2>(sm, w5, tid);
        run_layer<16, 4,  1>(sm, w6, tid);

        // store output: rows c*2+bi
        for (int i = tid; i < BT * 180; i += NT) {
            int bi = i / 180, r = i - bi * 180;
            int c = r / 45, k = r - c * 45;
            out[(b0 + bi) * 180 + r] = sm[O_AT + (c * 2 + bi) * ST + k];
        }
        __syncthreads();   // protect AT before next iteration's load
    }
}

extern "C" void kernel_launch(void* const* d_in, const int* in_sizes, int n_in,
                              void* d_out, int out_size)
{
    cudaFuncSetAttribute(scnn_kernel, cudaFuncAttributeMaxDynamicSharedMemorySize,
                         SMEM_BYTES);
    scnn_kernel<<<NBLK, NT, SMEM_BYTES>>>(
        (const float*)d_in[0], (const float*)d_in[1], (const float*)d_in[2],
        (const float*)d_in[3], (const float*)d_in[4], (const float*)d_in[5],
        (const float*)d_in[6], (const float*)d_in[7], (const float*)d_in[8],
        (float*)d_out);
}